// round 15
// baseline (speedup 1.0000x reference)
#include <cuda_runtime.h>
#include <cuda_fp16.h>
#include <cstdint>

#define FD 128
#define TM 128
#define NT 512             // 16 warps: 4 groups x 4 warps; group owns 32 rows
#define LDH 68             // smem row stride in words (64 half2 + 4 pad)

// ---------------- device scratch ----------------
__device__ float g_pred[4096];
__device__ float g_cnt[4096];
__device__ uint32_t g_WTq[FD * 64];        // [n][k] transposed, half2-packed
__device__ uint32_t g_WT1[FD * 64];
__device__ uint32_t g_WT2[FD * 64];
__device__ uint32_t g_embedh[500224 * 64]; // embed as half2 words

// ---------------- helpers ----------------
__device__ __forceinline__ uint32_t pack_h2(float a, float b) {
    __half2 h = __floats2half2_rn(a, b);
    return *reinterpret_cast<uint32_t*>(&h);
}
__device__ __forceinline__ float2 unpack_h2(uint32_t u) {
    __half2 h = *reinterpret_cast<__half2*>(&u);
    return __half22float2(h);
}
__device__ __forceinline__ float softplus_fast(float t) {
    return fmaxf(t, 0.0f) + __logf(1.0f + __expf(-fabsf(t)));
}
__device__ __forceinline__ float silu_fast(float v) {
    return __fdividef(v, 1.0f + __expf(-v));
}
__device__ __forceinline__ void mma16(float* c, const uint32_t* a, uint32_t b0, uint32_t b1) {
    asm volatile("mma.sync.aligned.m16n8k16.row.col.f32.f16.f16.f32 "
                 "{%0,%1,%2,%3}, {%4,%5,%6,%7}, {%8,%9}, {%0,%1,%2,%3};"
                 : "+f"(c[0]), "+f"(c[1]), "+f"(c[2]), "+f"(c[3])
                 : "r"(a[0]), "r"(a[1]), "r"(a[2]), "r"(a[3]), "r"(b0), "r"(b1));
}
#define LDSM4(r, addr)                                                        \
    asm volatile("ldmatrix.sync.aligned.m8n8.x4.shared.b16 {%0,%1,%2,%3}, [%4];" \
                 : "=r"((r)[0]), "=r"((r)[1]), "=r"((r)[2]), "=r"((r)[3])     \
                 : "r"(addr))
#define CP_ASYNC16(dst, src) \
    asm volatile("cp.async.cg.shared.global [%0], [%1], 16;" :: "r"(dst), "l"(src) : "memory")
#define CP_COMMIT() asm volatile("cp.async.commit_group;" ::: "memory")
#define CP_WAIT0()  asm volatile("cp.async.wait_group 0;" ::: "memory")
#define GBAR(id)    asm volatile("bar.sync %0, 128;" :: "r"(id) : "memory")

__device__ __forceinline__ uint32_t smem_u32(const void* p) {
    return (uint32_t)__cvta_generic_to_shared(p);
}

// 32-row group slice: warp computes 32x32 (validated R10/R12)
__device__ __forceinline__ void gemm_tile32(uint32_t smA, uint32_t smB,
                                            float acc[2][4][4], int mw, int nw, int lane) {
    #pragma unroll
    for (int i = 0; i < 2; i++)
        #pragma unroll
        for (int j = 0; j < 4; j++)
            #pragma unroll
            for (int e = 0; e < 4; e++) acc[i][j][e] = 0.0f;

    const int l7 = lane & 7;
    const int hi8 = (lane >> 3) & 1;
    const int hi16 = (lane >> 4) & 1;

    uint32_t aAddr0, aAddr1;
    {
        int r = mw + (lane & 15);
        int colw = hi16 ? 4 : 0;
        aAddr0 = smA + (uint32_t)(r * LDH + colw) * 4u;
        aAddr1 = aAddr0 + 16u * LDH * 4u;
    }
    uint32_t bAddr0, bAddr1;
    {
        int nrow = nw + l7 + (hi16 ? 8 : 0);
        int colw = hi8 ? 4 : 0;
        bAddr0 = smB + (uint32_t)(nrow * LDH + colw) * 4u;
        bAddr1 = bAddr0 + 16u * LDH * 4u;
    }

    #pragma unroll
    for (int ks = 0; ks < 8; ks++) {
        const uint32_t off = (uint32_t)ks * 32u;
        uint32_t a0[4], a1[4], b0[4], b1[4];
        LDSM4(a0, aAddr0 + off);
        LDSM4(a1, aAddr1 + off);
        LDSM4(b0, bAddr0 + off);
        LDSM4(b1, bAddr1 + off);
        mma16(acc[0][0], a0, b0[0], b0[1]);
        mma16(acc[0][1], a0, b0[2], b0[3]);
        mma16(acc[0][2], a0, b1[0], b1[1]);
        mma16(acc[0][3], a0, b1[2], b1[3]);
        mma16(acc[1][0], a1, b0[0], b0[1]);
        mma16(acc[1][1], a1, b0[2], b0[3]);
        mma16(acc[1][2], a1, b1[0], b1[1]);
        mma16(acc[1][3], a1, b1[2], b1[3]);
    }
}

// ---------------- prep ----------------
__global__ void prep_kernel(const float* __restrict__ Wq, const float* __restrict__ W1,
                            const float* __restrict__ W2, int B) {
    int i = blockIdx.x * blockDim.x + threadIdx.x;
    if (i < FD * 64) {
        int n = i >> 6, kw = i & 63;
        int k0 = kw * 2;
        g_WTq[i] = pack_h2(Wq[k0 * FD + n], Wq[(k0 + 1) * FD + n]);
        g_WT1[i] = pack_h2(W1[k0 * FD + n], W1[(k0 + 1) * FD + n]);
        g_WT2[i] = pack_h2(W2[k0 * FD + n], W2[(k0 + 1) * FD + n]);
    }
    if (i < B) { g_pred[i] = 0.0f; g_cnt[i] = 0.0f; }
}

__device__ __forceinline__ void cpa_weight(uint32_t dstAddr, const uint32_t* gw, int tid) {
    #pragma unroll
    for (int k = 0; k < 4; k++) {
        int i = tid + k * NT;
        int n = i >> 4, q = i & 15;
        CP_ASYNC16(dstAddr + (uint32_t)(n * LDH + q * 4) * 4u, gw + i * 4);
    }
}

// ---------------- pass1 (persistent): GEMM q + softplus -> embed + segment sums --------
__global__ __launch_bounds__(NT, 2)
void pass1_kernel(const float* __restrict__ x, const int* __restrict__ seg,
                  const float* __restrict__ E, const float* __restrict__ bq,
                  const float* __restrict__ Wk, const float* __restrict__ bk,
                  int N, int B, int nblk) {
    extern __shared__ uint32_t dyn[];
    uint32_t* As = dyn;
    const uint32_t AsA = smem_u32(As);
    const uint32_t WbA = AsA + TM * LDH * 4;
    __shared__ float rowsum[TM], eabs_sm[TM];
    __shared__ int segs_sm[TM];
    __shared__ float s_bq[FD], s_Wk[FD], s_bk[FD];

    const int tid = threadIdx.x, wid = tid >> 5, lane = tid & 31;
    const int grp = wid >> 2, gtid = tid & 127;
    const int lr0 = grp * 32;
    const int nw = (wid & 3) * 32;
    const int g = lane >> 2, t2 = (lane & 3) << 1;

    cpa_weight(WbA, g_WTq, tid);
    CP_COMMIT();
    if (tid < FD) { s_bq[tid] = bq[tid]; s_Wk[tid] = Wk[tid]; s_bk[tid] = bk[tid]; }
    CP_WAIT0();
    __syncthreads();

    for (int tile = blockIdx.x; tile < nblk; tile += gridDim.x) {
        const int m0 = tile * TM;

        if (gtid < 32) {
            int row = lr0 + gtid;
            int gr = min(m0 + row, N - 1);
            int sb = seg[gr]; sb = min(max(sb, 0), B - 1);
            segs_sm[row] = sb;
            eabs_sm[row] = fabsf(E[sb]);
            rowsum[row] = 0.0f;
        }
        #pragma unroll
        for (int it = 0; it < 8; it++) {
            int i = gtid + it * 128;
            int r = lr0 + (i >> 5), c = (i & 31) << 2;
            int gr = min(m0 + r, N - 1);
            float4 v = __ldcs((const float4*)(x + (size_t)gr * FD + c));
            *(uint2*)(As + r * LDH + (c >> 1)) =
                make_uint2(pack_h2(v.x, v.y), pack_h2(v.z, v.w));
        }
        GBAR(1 + grp);

        float acc[2][4][4];
        gemm_tile32(AsA, WbA, acc, lr0, nw, lane);

        #pragma unroll
        for (int i = 0; i < 2; i++) {
            #pragma unroll
            for (int e2 = 0; e2 < 2; e2++) {
                int rl = lr0 + 16 * i + g + 8 * e2;
                int gr = m0 + rl;
                float ea = eabs_sm[rl];
                float part = 0.0f;
                #pragma unroll
                for (int j = 0; j < 4; j++) {
                    int col = nw + 8 * j + t2;
                    float q0 = acc[i][j][e2 * 2] + s_bq[col];
                    float q1 = acc[i][j][e2 * 2 + 1] + s_bq[col + 1];
                    float v0 = softplus_fast(fmaf(ea, s_Wk[col], s_bk[col]) * q0);
                    float v1 = softplus_fast(fmaf(ea, s_Wk[col + 1], s_bk[col + 1]) * q1);
                    part += v0 + v1;
                    if (gr < N)
                        g_embedh[(size_t)gr * 64 + (col >> 1)] = pack_h2(v0, v1);
                }
                part += __shfl_xor_sync(0xffffffffu, part, 1);
                part += __shfl_xor_sync(0xffffffffu, part, 2);
                if ((lane & 3) == 0) atomicAdd(&rowsum[rl], part);
            }
        }
        GBAR(1 + grp);

        // reduce by group's warp0 — same warp writes next-tile metadata, so no
        // trailing barrier needed (program order within warp; others fenced by GBAR#1)
        if (gtid < 32) {
            int row = lr0 + gtid;
            bool head = (gtid == 0) || (segs_sm[row] != segs_sm[row - 1]);
            if (head && (m0 + row) < N) {
                int sh = segs_sm[row];
                float s = 0.0f, c = 0.0f;
                for (int j = gtid; j < 32 && segs_sm[lr0 + j] == sh && (m0 + lr0 + j) < N; j++) {
                    s += rowsum[lr0 + j];
                    c += 1.0f;
                }
                atomicAdd(&g_pred[sh], s);
                atomicAdd(&g_cnt[sh], c);
            }
        }
    }
}

// ---------------- pass2 (persistent): embed -> 2 chained GEMMs -> out ----------------
__device__ __forceinline__ float dval_of(const int* __restrict__ seg,
                                         const float* __restrict__ E, int gr, int B) {
    int sb = seg[gr]; sb = min(max(sb, 0), B - 1);
    return (E[sb] - g_pred[sb]) / g_cnt[sb] * (1.0f / 128.0f);
}

__global__ __launch_bounds__(NT, 2)
void pass2_kernel(const int* __restrict__ seg, const float* __restrict__ E,
                  const float* __restrict__ b1, const float* __restrict__ b2,
                  float* __restrict__ out, int N, int B, int nblk) {
    extern __shared__ uint32_t dyn[];
    uint32_t* As = dyn;
    const uint32_t AsA = smem_u32(As);
    const uint32_t BsA  = AsA + TM * LDH * 4;      // W1
    const uint32_t Bs2A = BsA + TM * LDH * 4;      // W2
    __shared__ float s_b1[FD], s_b2[FD];

    const int tid = threadIdx.x, wid = tid >> 5, lane = tid & 31;
    const int grp = wid >> 2, gtid = tid & 127;
    const int lr0 = grp * 32;
    const int nw = (wid & 3) * 32;
    const int g = lane >> 2, t2 = (lane & 3) << 1;

    cpa_weight(BsA, g_WT1, tid);
    cpa_weight(Bs2A, g_WT2, tid);
    CP_COMMIT();
    if (tid < FD) { s_b1[tid] = b1[tid]; s_b2[tid] = b2[tid]; }
    CP_WAIT0();
    __syncthreads();

    for (int tile = blockIdx.x; tile < nblk; tile += gridDim.x) {
        const int m0 = tile * TM;

        // load embed rows, inline dval, build silu(embed + d) -> As
        #pragma unroll
        for (int it = 0; it < 4; it++) {
            int i = gtid + it * 128;
            int r = lr0 + (i >> 4), wq = (i & 15) << 2;
            int gr = min(m0 + r, N - 1);
            uint4 u = *(const uint4*)(g_embedh + (size_t)gr * 64 + wq);
            float dd = dval_of(seg, E, gr, B);
            uint32_t w[4] = {u.x, u.y, u.z, u.w};
            #pragma unroll
            for (int q = 0; q < 4; q++) {
                float2 e = unpack_h2(w[q]);
                As[r * LDH + wq + q] = pack_h2(silu_fast(e.x + dd), silu_fast(e.y + dd));
            }
        }
        GBAR(1 + grp);

        float acc[2][4][4];
        gemm_tile32(AsA, BsA, acc, lr0, nw, lane);

        #pragma unroll
        for (int i = 0; i < 2; i++)
            #pragma unroll
            for (int j = 0; j < 4; j++)
                #pragma unroll
                for (int e = 0; e < 4; e++) {
                    int col = nw + 8 * j + t2 + (e & 1);
                    acc[i][j][e] = silu_fast(acc[i][j][e] + s_b1[col]);
                }
        GBAR(1 + grp);

        #pragma unroll
        for (int i = 0; i < 2; i++)
            #pragma unroll
            for (int e2 = 0; e2 < 2; e2++) {
                int rl = lr0 + 16 * i + g + 8 * e2;
                #pragma unroll
                for (int j = 0; j < 4; j++)
                    As[rl * LDH + ((nw + 8 * j + t2) >> 1)] =
                        pack_h2(acc[i][j][e2 * 2], acc[i][j][e2 * 2 + 1]);
            }
        GBAR(1 + grp);

        gemm_tile32(AsA, Bs2A, acc, lr0, nw, lane);

        // epilogue: out = (embed + d) + h2 + b2 (inline dval, streaming store)
        #pragma unroll
        for (int i = 0; i < 2; i++)
            #pragma unroll
            for (int e2 = 0; e2 < 2; e2++) {
                int rl = lr0 + 16 * i + g + 8 * e2;
                int gr = m0 + rl;
                if (gr < N) {
                    float dd = dval_of(seg, E, gr, B);
                    #pragma unroll
                    for (int j = 0; j < 4; j++) {
                        int col = nw + 8 * j + t2;
                        float2 e = unpack_h2(g_embedh[(size_t)gr * 64 + (col >> 1)]);
                        float2 o;
                        o.x = e.x + dd + acc[i][j][e2 * 2]     + s_b2[col];
                        o.y = e.y + dd + acc[i][j][e2 * 2 + 1] + s_b2[col + 1];
                        __stcs((float2*)(out + (size_t)gr * FD + col), o);
                    }
                }
            }
        GBAR(1 + grp);   // GEMM3 As reads done before next-tile As build
    }
}

// ---------------------------------------------------------------------------
extern "C" void kernel_launch(void* const* d_in, const int* in_sizes, int n_in,
                              void* d_out, int out_size) {
    const float* x   = (const float*)d_in[0];
    const float* E   = (const float*)d_in[1];
    const int*   seg = (const int*)d_in[3];
    const float* Wq  = (const float*)d_in[4];
    const float* bq  = (const float*)d_in[5];
    const float* Wk  = (const float*)d_in[6];
    const float* bk  = (const float*)d_in[7];
    const float* W1  = (const float*)d_in[8];
    const float* b1  = (const float*)d_in[9];
    const float* W2  = (const float*)d_in[10];
    const float* b2  = (const float*)d_in[11];
    float* out = (float*)d_out;

    const int N = in_sizes[0] / FD;
    const int B = in_sizes[1];
    const int nblk = (N + TM - 1) / TM;
    const int grid = min(nblk, 296);   // 2 CTAs per SM, persistent

    const int smem1 = 2 * TM * LDH * 4;   // 69632
    const int smem2 = 3 * TM * LDH * 4;   // 104448
    cudaFuncSetAttribute(pass1_kernel, cudaFuncAttributeMaxDynamicSharedMemorySize, smem1);
    cudaFuncSetAttribute(pass2_kernel, cudaFuncAttributeMaxDynamicSharedMemorySize, smem2);

    prep_kernel<<<(FD * 64 + 255) / 256, 256>>>(Wq, W1, W2, B);

    pass1_kernel<<<grid, NT, smem1>>>(x, seg, E, bq, Wk, bk, N, B, nblk);
    pass2_kernel<<<grid, NT, smem2>>>(seg, E, b1, b2, out, N, B, nblk);
}

// round 16
// speedup vs baseline: 1.0242x; 1.0242x over previous
#include <cuda_runtime.h>
#include <cuda_fp16.h>
#include <cstdint>

#define FD 128
#define TM 128
#define NT 512             // 16 warps: 4 groups x 4 warps; group owns 32 rows
#define LDH 68             // smem row stride in words (64 half2 + 4 pad)

// ---------------- device scratch ----------------
__device__ float g_pred[4096];
__device__ float g_cnt[4096];
__device__ uint32_t g_WTq[FD * 64];        // [n][k] transposed, half2-packed
__device__ uint32_t g_WT1[FD * 64];
__device__ uint32_t g_WT2[FD * 64];
__device__ uint32_t g_embedh[500224 * 64]; // embed as half2 words

// ---------------- helpers ----------------
__device__ __forceinline__ uint32_t pack_h2(float a, float b) {
    __half2 h = __floats2half2_rn(a, b);
    return *reinterpret_cast<uint32_t*>(&h);
}
__device__ __forceinline__ float2 unpack_h2(uint32_t u) {
    __half2 h = *reinterpret_cast<__half2*>(&u);
    return __half22float2(h);
}
__device__ __forceinline__ float softplus_fast(float t) {
    return fmaxf(t, 0.0f) + __logf(1.0f + __expf(-fabsf(t)));
}
__device__ __forceinline__ float silu_fast(float v) {
    return __fdividef(v, 1.0f + __expf(-v));
}
__device__ __forceinline__ void mma16(float* c, const uint32_t* a, uint32_t b0, uint32_t b1) {
    asm volatile("mma.sync.aligned.m16n8k16.row.col.f32.f16.f16.f32 "
                 "{%0,%1,%2,%3}, {%4,%5,%6,%7}, {%8,%9}, {%0,%1,%2,%3};"
                 : "+f"(c[0]), "+f"(c[1]), "+f"(c[2]), "+f"(c[3])
                 : "r"(a[0]), "r"(a[1]), "r"(a[2]), "r"(a[3]), "r"(b0), "r"(b1));
}
#define LDSM4(r, addr)                                                        \
    asm volatile("ldmatrix.sync.aligned.m8n8.x4.shared.b16 {%0,%1,%2,%3}, [%4];" \
                 : "=r"((r)[0]), "=r"((r)[1]), "=r"((r)[2]), "=r"((r)[3])     \
                 : "r"(addr))
#define CP_ASYNC16(dst, src) \
    asm volatile("cp.async.cg.shared.global [%0], [%1], 16;" :: "r"(dst), "l"(src) : "memory")
#define CP_COMMIT() asm volatile("cp.async.commit_group;" ::: "memory")
#define CP_WAIT0()  asm volatile("cp.async.wait_group 0;" ::: "memory")
#define GBAR(id)    asm volatile("bar.sync %0, 128;" :: "r"(id) : "memory")

__device__ __forceinline__ uint32_t smem_u32(const void* p) {
    return (uint32_t)__cvta_generic_to_shared(p);
}

// 32-row group slice: warp computes 32x32 (validated R10/R12)
__device__ __forceinline__ void gemm_tile32(uint32_t smA, uint32_t smB,
                                            float acc[2][4][4], int mw, int nw, int lane) {
    #pragma unroll
    for (int i = 0; i < 2; i++)
        #pragma unroll
        for (int j = 0; j < 4; j++)
            #pragma unroll
            for (int e = 0; e < 4; e++) acc[i][j][e] = 0.0f;

    const int l7 = lane & 7;
    const int hi8 = (lane >> 3) & 1;
    const int hi16 = (lane >> 4) & 1;

    uint32_t aAddr0, aAddr1;
    {
        int r = mw + (lane & 15);
        int colw = hi16 ? 4 : 0;
        aAddr0 = smA + (uint32_t)(r * LDH + colw) * 4u;
        aAddr1 = aAddr0 + 16u * LDH * 4u;
    }
    uint32_t bAddr0, bAddr1;
    {
        int nrow = nw + l7 + (hi16 ? 8 : 0);
        int colw = hi8 ? 4 : 0;
        bAddr0 = smB + (uint32_t)(nrow * LDH + colw) * 4u;
        bAddr1 = bAddr0 + 16u * LDH * 4u;
    }

    #pragma unroll
    for (int ks = 0; ks < 8; ks++) {
        const uint32_t off = (uint32_t)ks * 32u;
        uint32_t a0[4], a1[4], b0[4], b1[4];
        LDSM4(a0, aAddr0 + off);
        LDSM4(a1, aAddr1 + off);
        LDSM4(b0, bAddr0 + off);
        LDSM4(b1, bAddr1 + off);
        mma16(acc[0][0], a0, b0[0], b0[1]);
        mma16(acc[0][1], a0, b0[2], b0[3]);
        mma16(acc[0][2], a0, b1[0], b1[1]);
        mma16(acc[0][3], a0, b1[2], b1[3]);
        mma16(acc[1][0], a1, b0[0], b0[1]);
        mma16(acc[1][1], a1, b0[2], b0[3]);
        mma16(acc[1][2], a1, b1[0], b1[1]);
        mma16(acc[1][3], a1, b1[2], b1[3]);
    }
}

// ---------------- prep ----------------
__global__ void prep_kernel(const float* __restrict__ Wq, const float* __restrict__ W1,
                            const float* __restrict__ W2, int B) {
    int i = blockIdx.x * blockDim.x + threadIdx.x;
    if (i < FD * 64) {
        int n = i >> 6, kw = i & 63;
        int k0 = kw * 2;
        g_WTq[i] = pack_h2(Wq[k0 * FD + n], Wq[(k0 + 1) * FD + n]);
        g_WT1[i] = pack_h2(W1[k0 * FD + n], W1[(k0 + 1) * FD + n]);
        g_WT2[i] = pack_h2(W2[k0 * FD + n], W2[(k0 + 1) * FD + n]);
    }
    if (i < B) { g_pred[i] = 0.0f; g_cnt[i] = 0.0f; }
}

__device__ __forceinline__ void cpa_weight(uint32_t dstAddr, const uint32_t* gw, int tid) {
    #pragma unroll
    for (int k = 0; k < 4; k++) {
        int i = tid + k * NT;
        int n = i >> 4, q = i & 15;
        CP_ASYNC16(dstAddr + (uint32_t)(n * LDH + q * 4) * 4u, gw + i * 4);
    }
}

// ---------------- pass1 (persistent, double-buffered As) ----------------
__global__ __launch_bounds__(NT, 2)
void pass1_kernel(const float* __restrict__ x, const int* __restrict__ seg,
                  const float* __restrict__ E, const float* __restrict__ bq,
                  const float* __restrict__ Wk, const float* __restrict__ bk,
                  int N, int B, int nblk) {
    extern __shared__ uint32_t dyn[];
    uint32_t* As0 = dyn;                        // buffer 0
    uint32_t* As1 = dyn + TM * LDH;             // buffer 1
    const uint32_t As0A = smem_u32(As0);
    const uint32_t As1A = As0A + TM * LDH * 4;
    const uint32_t WbA  = As0A + 2 * TM * LDH * 4;
    __shared__ float rowsum[TM], eabs_sm[TM];
    __shared__ int segs_sm[TM];
    __shared__ float s_bq[FD], s_Wk[FD], s_bk[FD];

    const int tid = threadIdx.x, wid = tid >> 5, lane = tid & 31;
    const int grp = wid >> 2, gtid = tid & 127;
    const int lr0 = grp * 32;
    const int nw = (wid & 3) * 32;
    const int g = lane >> 2, t2 = (lane & 3) << 1;

    cpa_weight(WbA, g_WTq, tid);
    CP_COMMIT();
    if (tid < FD) { s_bq[tid] = bq[tid]; s_Wk[tid] = Wk[tid]; s_bk[tid] = bk[tid]; }
    CP_WAIT0();
    __syncthreads();

    // x loader for the group's 32 rows into a given buffer
    auto xload = [&](int m0, uint32_t* Ab) {
        #pragma unroll
        for (int it = 0; it < 8; it++) {
            int i = gtid + it * 128;
            int r = lr0 + (i >> 5), c = (i & 31) << 2;
            int gr = min(m0 + r, N - 1);
            float4 v = *(const float4*)(x + (size_t)gr * FD + c);
            *(uint2*)(Ab + r * LDH + (c >> 1)) =
                make_uint2(pack_h2(v.x, v.y), pack_h2(v.z, v.w));
        }
    };
    auto meta = [&](int m0) {
        if (gtid < 32) {
            int row = lr0 + gtid;
            int gr = min(m0 + row, N - 1);
            int sb = seg[gr]; sb = min(max(sb, 0), B - 1);
            segs_sm[row] = sb;
            eabs_sm[row] = fabsf(E[sb]);
            rowsum[row] = 0.0f;
        }
    };

    int tile = blockIdx.x;
    int buf = 0;
    if (tile < nblk) { meta(tile * TM); xload(tile * TM, As0); }

    for (; tile < nblk; tile += gridDim.x) {
        const int m0 = tile * TM;
        const uint32_t AcurA = buf ? As1A : As0A;
        uint32_t* Anxt = buf ? As0 : As1;

        GBAR(1 + grp);          // As[buf] + metadata ready for this tile

        float acc[2][4][4];
        gemm_tile32(AcurA, WbA, acc, lr0, nw, lane);

        // epilogue: softplus + direct embed store + row partial sums
        #pragma unroll
        for (int i = 0; i < 2; i++) {
            #pragma unroll
            for (int e2 = 0; e2 < 2; e2++) {
                int rl = lr0 + 16 * i + g + 8 * e2;
                int gr = m0 + rl;
                float ea = eabs_sm[rl];
                float part = 0.0f;
                #pragma unroll
                for (int j = 0; j < 4; j++) {
                    int col = nw + 8 * j + t2;
                    float q0 = acc[i][j][e2 * 2] + s_bq[col];
                    float q1 = acc[i][j][e2 * 2 + 1] + s_bq[col + 1];
                    float v0 = softplus_fast(fmaf(ea, s_Wk[col], s_bk[col]) * q0);
                    float v1 = softplus_fast(fmaf(ea, s_Wk[col + 1], s_bk[col + 1]) * q1);
                    part += v0 + v1;
                    if (gr < N)
                        g_embedh[(size_t)gr * 64 + (col >> 1)] = pack_h2(v0, v1);
                }
                part += __shfl_xor_sync(0xffffffffu, part, 1);
                part += __shfl_xor_sync(0xffffffffu, part, 2);
                if ((lane & 3) == 0) atomicAdd(&rowsum[rl], part);
            }
        }

        // prefetch next tile's x into the other buffer (latency hides behind
        // the barrier wait + reduce below)
        const int nt = tile + gridDim.x;
        if (nt < nblk) xload(nt * TM, Anxt);

        GBAR(1 + grp);          // rowsum complete; As[nxt] writes complete

        // reduce current tile, then write next tile's metadata (same warp,
        // program order; other warps blocked at next iteration's GBAR)
        if (gtid < 32) {
            int row = lr0 + gtid;
            bool head = (gtid == 0) || (segs_sm[row] != segs_sm[row - 1]);
            if (head && (m0 + row) < N) {
                int sh = segs_sm[row];
                float s = 0.0f, c = 0.0f;
                for (int j = gtid; j < 32 && segs_sm[lr0 + j] == sh && (m0 + lr0 + j) < N; j++) {
                    s += rowsum[lr0 + j];
                    c += 1.0f;
                }
                atomicAdd(&g_pred[sh], s);
                atomicAdd(&g_cnt[sh], c);
            }
        }
        if (nt < nblk) meta(nt * TM);
        buf ^= 1;
    }
}

// ---------------- pass2 (persistent): embed -> 2 chained GEMMs -> out (R14 form) -------
__global__ __launch_bounds__(NT, 2)
void pass2_kernel(const int* __restrict__ seg, const float* __restrict__ E,
                  const float* __restrict__ b1, const float* __restrict__ b2,
                  float* __restrict__ out, int N, int B, int nblk) {
    extern __shared__ uint32_t dyn[];
    uint32_t* As = dyn;
    const uint32_t AsA = smem_u32(As);
    const uint32_t BsA  = AsA + TM * LDH * 4;      // W1
    const uint32_t Bs2A = BsA + TM * LDH * 4;      // W2
    __shared__ float dval[TM];
    __shared__ float s_b1[FD], s_b2[FD];

    const int tid = threadIdx.x, wid = tid >> 5, lane = tid & 31;
    const int grp = wid >> 2, gtid = tid & 127;
    const int lr0 = grp * 32;
    const int nw = (wid & 3) * 32;
    const int g = lane >> 2, t2 = (lane & 3) << 1;

    cpa_weight(BsA, g_WT1, tid);
    cpa_weight(Bs2A, g_WT2, tid);
    CP_COMMIT();
    if (tid < FD) { s_b1[tid] = b1[tid]; s_b2[tid] = b2[tid]; }
    CP_WAIT0();
    __syncthreads();

    for (int tile = blockIdx.x; tile < nblk; tile += gridDim.x) {
        const int m0 = tile * TM;

        if (gtid < 32) {
            int row = lr0 + gtid;
            int gr = min(m0 + row, N - 1);
            int sb = seg[gr]; sb = min(max(sb, 0), B - 1);
            dval[row] = (E[sb] - g_pred[sb]) / g_cnt[sb] * (1.0f / 128.0f);
        }
        GBAR(1 + grp);

        #pragma unroll
        for (int it = 0; it < 4; it++) {
            int i = gtid + it * 128;
            int r = lr0 + (i >> 4), wq = (i & 15) << 2;
            int gr = min(m0 + r, N - 1);
            uint4 u = *(const uint4*)(g_embedh + (size_t)gr * 64 + wq);
            float dd = dval[r];
            uint32_t w[4] = {u.x, u.y, u.z, u.w};
            #pragma unroll
            for (int q = 0; q < 4; q++) {
                float2 e = unpack_h2(w[q]);
                As[r * LDH + wq + q] = pack_h2(silu_fast(e.x + dd), silu_fast(e.y + dd));
            }
        }
        GBAR(1 + grp);

        float acc[2][4][4];
        gemm_tile32(AsA, BsA, acc, lr0, nw, lane);

        #pragma unroll
        for (int i = 0; i < 2; i++)
            #pragma unroll
            for (int j = 0; j < 4; j++)
                #pragma unroll
                for (int e = 0; e < 4; e++) {
                    int col = nw + 8 * j + t2 + (e & 1);
                    acc[i][j][e] = silu_fast(acc[i][j][e] + s_b1[col]);
                }
        GBAR(1 + grp);

        #pragma unroll
        for (int i = 0; i < 2; i++)
            #pragma unroll
            for (int e2 = 0; e2 < 2; e2++) {
                int rl = lr0 + 16 * i + g + 8 * e2;
                #pragma unroll
                for (int j = 0; j < 4; j++)
                    As[rl * LDH + ((nw + 8 * j + t2) >> 1)] =
                        pack_h2(acc[i][j][e2 * 2], acc[i][j][e2 * 2 + 1]);
            }
        GBAR(1 + grp);

        gemm_tile32(AsA, Bs2A, acc, lr0, nw, lane);

        #pragma unroll
        for (int i = 0; i < 2; i++)
            #pragma unroll
            for (int e2 = 0; e2 < 2; e2++) {
                int rl = lr0 + 16 * i + g + 8 * e2;
                int gr = m0 + rl;
                if (gr < N) {
                    float dd = dval[rl];
                    #pragma unroll
                    for (int j = 0; j < 4; j++) {
                        int col = nw + 8 * j + t2;
                        float2 e = unpack_h2(g_embedh[(size_t)gr * 64 + (col >> 1)]);
                        float2 o;
                        o.x = e.x + dd + acc[i][j][e2 * 2]     + s_b2[col];
                        o.y = e.y + dd + acc[i][j][e2 * 2 + 1] + s_b2[col + 1];
                        *(float2*)(out + (size_t)gr * FD + col) = o;
                    }
                }
            }
        GBAR(1 + grp);
    }
}

// ---------------------------------------------------------------------------
extern "C" void kernel_launch(void* const* d_in, const int* in_sizes, int n_in,
                              void* d_out, int out_size) {
    const float* x   = (const float*)d_in[0];
    const float* E   = (const float*)d_in[1];
    const int*   seg = (const int*)d_in[3];
    const float* Wq  = (const float*)d_in[4];
    const float* bq  = (const float*)d_in[5];
    const float* Wk  = (const float*)d_in[6];
    const float* bk  = (const float*)d_in[7];
    const float* W1  = (const float*)d_in[8];
    const float* b1  = (const float*)d_in[9];
    const float* W2  = (const float*)d_in[10];
    const float* b2  = (const float*)d_in[11];
    float* out = (float*)d_out;

    const int N = in_sizes[0] / FD;
    const int B = in_sizes[1];
    const int nblk = (N + TM - 1) / TM;
    const int grid = min(nblk, 296);   // 2 CTAs per SM, persistent

    const int smem1 = 3 * TM * LDH * 4;   // 104448 (As x2 + W)
    const int smem2 = 3 * TM * LDH * 4;   // 104448 (As + W1 + W2)
    cudaFuncSetAttribute(pass1_kernel, cudaFuncAttributeMaxDynamicSharedMemorySize, smem1);
    cudaFuncSetAttribute(pass2_kernel, cudaFuncAttributeMaxDynamicSharedMemorySize, smem2);

    prep_kernel<<<(FD * 64 + 255) / 256, 256>>>(Wq, W1, W2, B);

    pass1_kernel<<<grid, NT, smem1>>>(x, seg, E, bq, Wk, bk, N, B, nblk);
    pass2_kernel<<<grid, NT, smem2>>>(seg, E, b1, b2, out, N, B, nblk);
}

// round 17
// speedup vs baseline: 1.0604x; 1.0354x over previous
#include <cuda_runtime.h>
#include <cuda_fp16.h>
#include <cstdint>

#define FD 128
#define TM 128
#define NT 512             // 16 warps: 4 groups x 4 warps; group owns 32 rows
#define LDH 68             // smem row stride in words (64 half2 + 4 pad)

// ---------------- device scratch ----------------
__device__ float g_pred[4096];
__device__ float g_cnt[4096];
__device__ uint32_t g_WTq[FD * 64];        // [n][k] transposed, half2-packed
__device__ uint32_t g_WT1[FD * 64];
__device__ uint32_t g_WT2[FD * 64];
__device__ uint32_t g_embedh[500224 * 64]; // embed as half2 words

// ---------------- helpers ----------------
__device__ __forceinline__ uint32_t pack_h2(float a, float b) {
    __half2 h = __floats2half2_rn(a, b);
    return *reinterpret_cast<uint32_t*>(&h);
}
__device__ __forceinline__ float2 unpack_h2(uint32_t u) {
    __half2 h = *reinterpret_cast<__half2*>(&u);
    return __half22float2(h);
}
__device__ __forceinline__ float softplus_fast(float t) {
    return fmaxf(t, 0.0f) + __logf(1.0f + __expf(-fabsf(t)));
}
// silu on packed half2: silu(x) = (x/2) * (1 + tanh(x/2)); 1 tanh.f16x2 per 2 elems
__device__ __forceinline__ uint32_t silu_h2(uint32_t xu) {
    __half2 x = *reinterpret_cast<__half2*>(&xu);
    __half2 xh = __hmul2(x, __float2half2_rn(0.5f));
    uint32_t xhu = *reinterpret_cast<uint32_t*>(&xh);
    uint32_t tu;
    asm("tanh.approx.f16x2 %0, %1;" : "=r"(tu) : "r"(xhu));
    __half2 t = *reinterpret_cast<__half2*>(&tu);
    __half2 r = __hmul2(xh, __hadd2(t, __float2half2_rn(1.0f)));
    return *reinterpret_cast<uint32_t*>(&r);
}
__device__ __forceinline__ void mma16(float* c, const uint32_t* a, uint32_t b0, uint32_t b1) {
    asm volatile("mma.sync.aligned.m16n8k16.row.col.f32.f16.f16.f32 "
                 "{%0,%1,%2,%3}, {%4,%5,%6,%7}, {%8,%9}, {%0,%1,%2,%3};"
                 : "+f"(c[0]), "+f"(c[1]), "+f"(c[2]), "+f"(c[3])
                 : "r"(a[0]), "r"(a[1]), "r"(a[2]), "r"(a[3]), "r"(b0), "r"(b1));
}
#define LDSM4(r, addr)                                                        \
    asm volatile("ldmatrix.sync.aligned.m8n8.x4.shared.b16 {%0,%1,%2,%3}, [%4];" \
                 : "=r"((r)[0]), "=r"((r)[1]), "=r"((r)[2]), "=r"((r)[3])     \
                 : "r"(addr))
#define CP_ASYNC16(dst, src) \
    asm volatile("cp.async.cg.shared.global [%0], [%1], 16;" :: "r"(dst), "l"(src) : "memory")
#define CP_COMMIT() asm volatile("cp.async.commit_group;" ::: "memory")
#define CP_WAIT0()  asm volatile("cp.async.wait_group 0;" ::: "memory")
#define GBAR(id)    asm volatile("bar.sync %0, 128;" :: "r"(id) : "memory")

__device__ __forceinline__ uint32_t smem_u32(const void* p) {
    return (uint32_t)__cvta_generic_to_shared(p);
}

// 32-row group slice: warp computes 32x32 (validated R10/R12)
__device__ __forceinline__ void gemm_tile32(uint32_t smA, uint32_t smB,
                                            float acc[2][4][4], int mw, int nw, int lane) {
    #pragma unroll
    for (int i = 0; i < 2; i++)
        #pragma unroll
        for (int j = 0; j < 4; j++)
            #pragma unroll
            for (int e = 0; e < 4; e++) acc[i][j][e] = 0.0f;

    const int l7 = lane & 7;
    const int hi8 = (lane >> 3) & 1;
    const int hi16 = (lane >> 4) & 1;

    uint32_t aAddr0, aAddr1;
    {
        int r = mw + (lane & 15);
        int colw = hi16 ? 4 : 0;
        aAddr0 = smA + (uint32_t)(r * LDH + colw) * 4u;
        aAddr1 = aAddr0 + 16u * LDH * 4u;
    }
    uint32_t bAddr0, bAddr1;
    {
        int nrow = nw + l7 + (hi16 ? 8 : 0);
        int colw = hi8 ? 4 : 0;
        bAddr0 = smB + (uint32_t)(nrow * LDH + colw) * 4u;
        bAddr1 = bAddr0 + 16u * LDH * 4u;
    }

    #pragma unroll
    for (int ks = 0; ks < 8; ks++) {
        const uint32_t off = (uint32_t)ks * 32u;
        uint32_t a0[4], a1[4], b0[4], b1[4];
        LDSM4(a0, aAddr0 + off);
        LDSM4(a1, aAddr1 + off);
        LDSM4(b0, bAddr0 + off);
        LDSM4(b1, bAddr1 + off);
        mma16(acc[0][0], a0, b0[0], b0[1]);
        mma16(acc[0][1], a0, b0[2], b0[3]);
        mma16(acc[0][2], a0, b1[0], b1[1]);
        mma16(acc[0][3], a0, b1[2], b1[3]);
        mma16(acc[1][0], a1, b0[0], b0[1]);
        mma16(acc[1][1], a1, b0[2], b0[3]);
        mma16(acc[1][2], a1, b1[0], b1[1]);
        mma16(acc[1][3], a1, b1[2], b1[3]);
    }
}

// ---------------- prep ----------------
__global__ void prep_kernel(const float* __restrict__ Wq, const float* __restrict__ W1,
                            const float* __restrict__ W2, int B) {
    int i = blockIdx.x * blockDim.x + threadIdx.x;
    if (i < FD * 64) {
        int n = i >> 6, kw = i & 63;
        int k0 = kw * 2;
        g_WTq[i] = pack_h2(Wq[k0 * FD + n], Wq[(k0 + 1) * FD + n]);
        g_WT1[i] = pack_h2(W1[k0 * FD + n], W1[(k0 + 1) * FD + n]);
        g_WT2[i] = pack_h2(W2[k0 * FD + n], W2[(k0 + 1) * FD + n]);
    }
    if (i < B) { g_pred[i] = 0.0f; g_cnt[i] = 0.0f; }
}

__device__ __forceinline__ void cpa_weight(uint32_t dstAddr, const uint32_t* gw, int tid) {
    #pragma unroll
    for (int k = 0; k < 4; k++) {
        int i = tid + k * NT;
        int n = i >> 4, q = i & 15;
        CP_ASYNC16(dstAddr + (uint32_t)(n * LDH + q * 4) * 4u, gw + i * 4);
    }
}

// ---------------- pass1 (persistent): GEMM q + softplus -> embed + segment sums --------
__global__ __launch_bounds__(NT, 2)
void pass1_kernel(const float* __restrict__ x, const int* __restrict__ seg,
                  const float* __restrict__ E, const float* __restrict__ bq,
                  const float* __restrict__ Wk, const float* __restrict__ bk,
                  int N, int B, int nblk) {
    extern __shared__ uint32_t dyn[];
    uint32_t* As = dyn;
    const uint32_t AsA = smem_u32(As);
    const uint32_t WbA = AsA + TM * LDH * 4;
    __shared__ float rowsum[TM], eabs_sm[TM];
    __shared__ int segs_sm[TM];
    __shared__ float s_bq[FD], s_Wk[FD], s_bk[FD];

    const int tid = threadIdx.x, wid = tid >> 5, lane = tid & 31;
    const int grp = wid >> 2, gtid = tid & 127;
    const int lr0 = grp * 32;
    const int nw = (wid & 3) * 32;
    const int g = lane >> 2, t2 = (lane & 3) << 1;

    cpa_weight(WbA, g_WTq, tid);
    CP_COMMIT();
    if (tid < FD) { s_bq[tid] = bq[tid]; s_Wk[tid] = Wk[tid]; s_bk[tid] = bk[tid]; }
    CP_WAIT0();
    __syncthreads();

    for (int tile = blockIdx.x; tile < nblk; tile += gridDim.x) {
        const int m0 = tile * TM;

        if (gtid < 32) {
            int row = lr0 + gtid;
            int gr = min(m0 + row, N - 1);
            int sb = seg[gr]; sb = min(max(sb, 0), B - 1);
            segs_sm[row] = sb;
            eabs_sm[row] = fabsf(E[sb]);
            rowsum[row] = 0.0f;
        }
        #pragma unroll
        for (int it = 0; it < 8; it++) {
            int i = gtid + it * 128;
            int r = lr0 + (i >> 5), c = (i & 31) << 2;
            int gr = min(m0 + r, N - 1);
            float4 v = *(const float4*)(x + (size_t)gr * FD + c);
            *(uint2*)(As + r * LDH + (c >> 1)) =
                make_uint2(pack_h2(v.x, v.y), pack_h2(v.z, v.w));
        }
        GBAR(1 + grp);

        float acc[2][4][4];
        gemm_tile32(AsA, WbA, acc, lr0, nw, lane);

        #pragma unroll
        for (int i = 0; i < 2; i++) {
            #pragma unroll
            for (int e2 = 0; e2 < 2; e2++) {
                int rl = lr0 + 16 * i + g + 8 * e2;
                int gr = m0 + rl;
                float ea = eabs_sm[rl];
                float part = 0.0f;
                #pragma unroll
                for (int j = 0; j < 4; j++) {
                    int col = nw + 8 * j + t2;
                    float q0 = acc[i][j][e2 * 2] + s_bq[col];
                    float q1 = acc[i][j][e2 * 2 + 1] + s_bq[col + 1];
                    float v0 = softplus_fast(fmaf(ea, s_Wk[col], s_bk[col]) * q0);
                    float v1 = softplus_fast(fmaf(ea, s_Wk[col + 1], s_bk[col + 1]) * q1);
                    part += v0 + v1;
                    if (gr < N)
                        g_embedh[(size_t)gr * 64 + (col >> 1)] = pack_h2(v0, v1);
                }
                part += __shfl_xor_sync(0xffffffffu, part, 1);
                part += __shfl_xor_sync(0xffffffffu, part, 2);
                if ((lane & 3) == 0) atomicAdd(&rowsum[rl], part);
            }
        }
        GBAR(1 + grp);

        if (gtid < 32) {
            int row = lr0 + gtid;
            bool head = (gtid == 0) || (segs_sm[row] != segs_sm[row - 1]);
            if (head && (m0 + row) < N) {
                int sh = segs_sm[row];
                float s = 0.0f, c = 0.0f;
                for (int j = gtid; j < 32 && segs_sm[lr0 + j] == sh && (m0 + lr0 + j) < N; j++) {
                    s += rowsum[lr0 + j];
                    c += 1.0f;
                }
                atomicAdd(&g_pred[sh], s);
                atomicAdd(&g_cnt[sh], c);
            }
        }
        GBAR(1 + grp);     // reduce done before next tile's metadata overwrite
    }
}

// ---------------- pass2 (persistent): embed -> 2 chained GEMMs -> out ----------------
__global__ __launch_bounds__(NT, 2)
void pass2_kernel(const int* __restrict__ seg, const float* __restrict__ E,
                  const float* __restrict__ b1, const float* __restrict__ b2,
                  float* __restrict__ out, int N, int B, int nblk) {
    extern __shared__ uint32_t dyn[];
    uint32_t* As = dyn;
    const uint32_t AsA = smem_u32(As);
    const uint32_t BsA  = AsA + TM * LDH * 4;      // W1
    const uint32_t Bs2A = BsA + TM * LDH * 4;      // W2
    __shared__ float dval[TM];
    __shared__ float s_b1[FD], s_b2[FD];

    const int tid = threadIdx.x, wid = tid >> 5, lane = tid & 31;
    const int grp = wid >> 2, gtid = tid & 127;
    const int lr0 = grp * 32;
    const int nw = (wid & 3) * 32;
    const int g = lane >> 2, t2 = (lane & 3) << 1;

    cpa_weight(BsA, g_WT1, tid);
    cpa_weight(Bs2A, g_WT2, tid);
    CP_COMMIT();
    if (tid < FD) { s_b1[tid] = b1[tid]; s_b2[tid] = b2[tid]; }
    CP_WAIT0();
    __syncthreads();

    for (int tile = blockIdx.x; tile < nblk; tile += gridDim.x) {
        const int m0 = tile * TM;

        if (gtid < 32) {
            int row = lr0 + gtid;
            int gr = min(m0 + row, N - 1);
            int sb = seg[gr]; sb = min(max(sb, 0), B - 1);
            dval[row] = (E[sb] - g_pred[sb]) / g_cnt[sb] * (1.0f / 128.0f);
        }
        GBAR(1 + grp);

        // load embed rows, build silu(embed + d) -> As  (silu in half2 tanh form)
        #pragma unroll
        for (int it = 0; it < 4; it++) {
            int i = gtid + it * 128;
            int r = lr0 + (i >> 4), wq = (i & 15) << 2;
            int gr = min(m0 + r, N - 1);
            uint4 u = *(const uint4*)(g_embedh + (size_t)gr * 64 + wq);
            float dd = dval[r];
            uint32_t w[4] = {u.x, u.y, u.z, u.w};
            #pragma unroll
            for (int q = 0; q < 4; q++) {
                float2 e = unpack_h2(w[q]);
                As[r * LDH + wq + q] = silu_h2(pack_h2(e.x + dd, e.y + dd));
            }
        }
        GBAR(1 + grp);

        float acc[2][4][4];
        // GEMM2: h1 = silu(scale) @ W1
        gemm_tile32(AsA, BsA, acc, lr0, nw, lane);
        GBAR(1 + grp);     // group done reading its As rows

        // h = silu(h1 + b1) in half2 tanh form -> As
        #pragma unroll
        for (int i = 0; i < 2; i++)
            #pragma unroll
            for (int e2 = 0; e2 < 2; e2++) {
                int rl = lr0 + 16 * i + g + 8 * e2;
                #pragma unroll
                for (int j = 0; j < 4; j++) {
                    int col = nw + 8 * j + t2;
                    uint32_t p = pack_h2(acc[i][j][e2 * 2] + s_b1[col],
                                         acc[i][j][e2 * 2 + 1] + s_b1[col + 1]);
                    As[rl * LDH + (col >> 1)] = silu_h2(p);
                }
            }
        GBAR(1 + grp);

        // GEMM3: h2 = h @ W2
        gemm_tile32(AsA, Bs2A, acc, lr0, nw, lane);

        // direct fragment epilogue: out = (embed + d) + h2 + b2
        #pragma unroll
        for (int i = 0; i < 2; i++)
            #pragma unroll
            for (int e2 = 0; e2 < 2; e2++) {
                int rl = lr0 + 16 * i + g + 8 * e2;
                int gr = m0 + rl;
                if (gr < N) {
                    float dd = dval[rl];
                    #pragma unroll
                    for (int j = 0; j < 4; j++) {
                        int col = nw + 8 * j + t2;
                        float2 e = unpack_h2(g_embedh[(size_t)gr * 64 + (col >> 1)]);
                        float2 o;
                        o.x = e.x + dd + acc[i][j][e2 * 2]     + s_b2[col];
                        o.y = e.y + dd + acc[i][j][e2 * 2 + 1] + s_b2[col + 1];
                        *(float2*)(out + (size_t)gr * FD + col) = o;
                    }
                }
            }
        GBAR(1 + grp);     // epilogue reads dval done before next tile's overwrite
    }
}

// ---------------------------------------------------------------------------
extern "C" void kernel_launch(void* const* d_in, const int* in_sizes, int n_in,
                              void* d_out, int out_size) {
    const float* x   = (const float*)d_in[0];
    const float* E   = (const float*)d_in[1];
    const int*   seg = (const int*)d_in[3];
    const float* Wq  = (const float*)d_in[4];
    const float* bq  = (const float*)d_in[5];
    const float* Wk  = (const float*)d_in[6];
    const float* bk  = (const float*)d_in[7];
    const float* W1  = (const float*)d_in[8];
    const float* b1  = (const float*)d_in[9];
    const float* W2  = (const float*)d_in[10];
    const float* b2  = (const float*)d_in[11];
    float* out = (float*)d_out;

    const int N = in_sizes[0] / FD;
    const int B = in_sizes[1];
    const int nblk = (N + TM - 1) / TM;
    const int grid = min(nblk, 296);   // 2 CTAs per SM, persistent

    const int smem1 = 2 * TM * LDH * 4;   // 69632
    const int smem2 = 3 * TM * LDH * 4;   // 104448
    cudaFuncSetAttribute(pass1_kernel, cudaFuncAttributeMaxDynamicSharedMemorySize, smem1);
    cudaFuncSetAttribute(pass2_kernel, cudaFuncAttributeMaxDynamicSharedMemorySize, smem2);

    prep_kernel<<<(FD * 64 + 255) / 256, 256>>>(Wq, W1, W2, B);

    pass1_kernel<<<grid, NT, smem1>>>(x, seg, E, bq, Wk, bk, N, B, nblk);
    pass2_kernel<<<grid, NT, smem2>>>(seg, E, b1, b2, out, N, B, nblk);
}